// round 13
// baseline (speedup 1.0000x reference)
#include <cuda_runtime.h>
#include <cuda_fp16.h>
#include <math.h>
#include <stdint.h>

// ---------------------------------------------------------------------------
// Problem constants
// ---------------------------------------------------------------------------
#define BATCH   32
#define HW      32
#define C_DIM   384
#define NHEADS  12
#define HEADD   32
#define WS      8
#define SS      4
#define NTOK    64
#define M_TOK   (BATCH * HW * HW)      // 32768
#define QKV_N   (3 * C_DIM)            // 1152
#define HIDDEN  (4 * C_DIM)            // 1536
#define SCALE_ATTN 0.17677669529663687f

// ---------------------------------------------------------------------------
// Scratch (device globals; allocation is forbidden)
// ---------------------------------------------------------------------------
__device__ __align__(16) __half g_xw  [(size_t)M_TOK * C_DIM];
__device__ __align__(16) __half g_qkv [(size_t)M_TOK * QKV_N];
__device__ __align__(16) __half g_at  [(size_t)M_TOK * C_DIM];
__device__ __align__(16) float  g_x1  [(size_t)M_TOK * C_DIM];
__device__ __align__(16) __half g_n2  [(size_t)M_TOK * C_DIM];
__device__ __align__(16) __half g_h   [(size_t)M_TOK * HIDDEN];
// transposed fp16 weights [N][K]
__device__ __align__(16) __half g_wqkv[(size_t)QKV_N * C_DIM];
__device__ __align__(16) __half g_wpr [(size_t)C_DIM * C_DIM];
__device__ __align__(16) __half g_wf1 [(size_t)HIDDEN * C_DIM];
__device__ __align__(16) __half g_wf2 [(size_t)C_DIM * HIDDEN];

// ---------------------------------------------------------------------------
// helpers
// ---------------------------------------------------------------------------
__device__ __forceinline__ int win2img(int row) {
    int w  = row >> 6;
    int n  = row & 63;
    int b  = w >> 4;
    int wi = w & 15;
    int wh = wi >> 2, ww = wi & 3;
    int r  = n >> 3,  cc = n & 7;
    int i  = (wh * 8 + r + SS) & 31;
    int j  = (ww * 8 + cc + SS) & 31;
    return b * 1024 + i * 32 + j;
}

__device__ __forceinline__ float gelu_tanh(float x) {
    float x3 = x * x * x;
    return 0.5f * x * (1.0f + tanhf(0.7978845608028654f * (x + 0.044715f * x3)));
}

__device__ __forceinline__ uint32_t smem_u32(const void* p) {
    uint32_t a;
    asm("{ .reg .u64 t; cvta.to.shared.u64 t, %1; cvt.u32.u64 %0, t; }" : "=r"(a) : "l"(p));
    return a;
}

__device__ __forceinline__ uint32_t pkh2(__half a, __half b) {
    return (uint32_t)__half_as_ushort(a) | ((uint32_t)__half_as_ushort(b) << 16);
}

__device__ __forceinline__ void cpasync16(uint32_t dst, const void* src) {
    asm volatile("cp.async.cg.shared.global [%0], [%1], 16;" :: "r"(dst), "l"(src));
}

__device__ __forceinline__ void ldm4(uint32_t* r, uint32_t a) {
    asm volatile("ldmatrix.sync.aligned.m8n8.x4.shared.b16 {%0,%1,%2,%3}, [%4];"
                 : "=r"(r[0]), "=r"(r[1]), "=r"(r[2]), "=r"(r[3]) : "r"(a));
}
__device__ __forceinline__ void ldm4t(uint32_t* r, uint32_t a) {
    asm volatile("ldmatrix.sync.aligned.m8n8.x4.trans.shared.b16 {%0,%1,%2,%3}, [%4];"
                 : "=r"(r[0]), "=r"(r[1]), "=r"(r[2]), "=r"(r[3]) : "r"(a));
}
__device__ __forceinline__ void mma16816(float* c, const uint32_t* a, const uint32_t* b) {
    asm volatile("mma.sync.aligned.m16n8k16.row.col.f32.f16.f16.f32 "
                 "{%0,%1,%2,%3}, {%4,%5,%6,%7}, {%8,%9}, {%0,%1,%2,%3};"
                 : "+f"(c[0]), "+f"(c[1]), "+f"(c[2]), "+f"(c[3])
                 : "r"(a[0]), "r"(a[1]), "r"(a[2]), "r"(a[3]), "r"(b[0]), "r"(b[1]));
}

// ---------------------------------------------------------------------------
// single fused weight convert: all four fp32 [K,N] -> fp16 transposed [N,K]
// ---------------------------------------------------------------------------
__global__ void wconv_all(const float* __restrict__ w0, const float* __restrict__ w1,
                          const float* __restrict__ w2, const float* __restrict__ w3,
                          __half* __restrict__ o0, __half* __restrict__ o1,
                          __half* __restrict__ o2, __half* __restrict__ o3) {
    int idx = blockIdx.x * 256 + threadIdx.x;
    const float* w; __half* o; int N, K, off;
    if (idx < 442368)        { w = w0; o = o0; K = 384;  N = 1152; off = idx; }
    else if (idx < 589824)   { w = w1; o = o1; K = 384;  N = 384;  off = idx - 442368; }
    else if (idx < 1179648)  { w = w2; o = o2; K = 384;  N = 1536; off = idx - 589824; }
    else                     { w = w3; o = o3; K = 1536; N = 384;  off = idx - 1179648; }
    int k = off / N, n = off - k * N;
    o[(size_t)n * K + k] = __float2half_rn(w[off]);
}

// ---------------------------------------------------------------------------
// LayerNorm -> fp16. SHIFT gathers the shifted-window permutation.
// ---------------------------------------------------------------------------
template <bool SHIFT>
__global__ void ln_kernel(const float* __restrict__ x,
                          const float* __restrict__ gamma,
                          const float* __restrict__ beta,
                          __half* __restrict__ o) {
    int row = blockIdx.x;
    int src = SHIFT ? win2img(row) : row;
    const float* xp = x + (size_t)src * C_DIM;
    int tid = threadIdx.x;

    float v0 = xp[tid], v1 = xp[tid + 128], v2 = xp[tid + 256];
    float s  = v0 + v1 + v2;
    float sq = v0 * v0 + v1 * v1 + v2 * v2;
    #pragma unroll
    for (int off = 16; off > 0; off >>= 1) {
        s  += __shfl_down_sync(0xffffffffu, s,  off);
        sq += __shfl_down_sync(0xffffffffu, sq, off);
    }
    __shared__ float sa[4], sb[4];
    int wp = tid >> 5, ln = tid & 31;
    if (ln == 0) { sa[wp] = s; sb[wp] = sq; }
    __syncthreads();
    s  = sa[0] + sa[1] + sa[2] + sa[3];
    sq = sb[0] + sb[1] + sb[2] + sb[3];

    float mean = s * (1.0f / C_DIM);
    float var  = sq * (1.0f / C_DIM) - mean * mean;
    float inv  = rsqrtf(var + 1e-5f);

    size_t rb = (size_t)row * C_DIM;
    #pragma unroll
    for (int u = 0; u < 3; u++) {
        int c = tid + u * 128;
        float v = (u == 0 ? v0 : u == 1 ? v1 : v2);
        o[rb + c] = __float2half_rn((v - mean) * inv * gamma[c] + beta[c]);
    }
}

// ---------------------------------------------------------------------------
// fp16 HMMA GEMM: C = A[M,K] @ Bt[N,K]^T (+ bias + epilogue), fp32 accum.
// CTA tile 128x128, BK=64, 128 threads (4 warps 2x2, warp tile 64x64).
// Rationale: 64x64 warp tiles cut ldmatrix bytes per MMA 1.5x (LDSM-bound).
// 3-stage cp.async pipeline, one __syncthreads per k-iteration.
// EPI 0: bias -> fp16 out                          (qkv)
// EPI 1: bias + gelu -> fp16 out                   (fc1)
// EPI 2: bias + res[m] -> f32 out                  (fc2 + residual, final)
// EPI 3: bias + res[win2img(m)] -> f32 scattered   (proj + reverse + residual)
// ---------------------------------------------------------------------------
#define AS_STRIDE 72                      // halfs per row (64 + 8 pad) = 144 B
#define TILE_BYTES (128 * AS_STRIDE * 2)  // 18432 per tile
#define STAGE_BYTES (2 * TILE_BYTES)      // A + B = 36864
#define SMEM_BYTES (3 * STAGE_BYTES)      // 110592

template <int EPI>
__global__ __launch_bounds__(128)
void hgemm(const __half* __restrict__ A, const __half* __restrict__ B,
           const float* __restrict__ bias, const float* __restrict__ res,
           float* __restrict__ Cf, __half* __restrict__ Ch,
           int N, int K) {
    extern __shared__ __align__(16) char sm[];
    uint32_t sb = smem_u32(sm);

    int tid  = threadIdx.x;
    int lane = tid & 31;
    int wid  = tid >> 5;
    int warp_m = wid >> 1;       // 0..1 -> 64 rows
    int warp_n = wid & 1;        // 0..1 -> 64 cols
    int bm = blockIdx.y * 128, bn = blockIdx.x * 128;

    int lr = lane & 7;
    int aRow = warp_m * 64 + ((lane >> 3) & 1) * 8 + lr;   // + mt*16
    int aCol = (lane >> 4) * 8;
    int bRow = warp_n * 64 + ((lane >> 4) & 1) * 8 + lr;   // + np*16
    int bCol = ((lane >> 3) & 1) * 8;

    float acc[4][8][4];
    #pragma unroll
    for (int i = 0; i < 4; i++)
        #pragma unroll
        for (int j = 0; j < 8; j++)
            #pragma unroll
            for (int e = 0; e < 4; e++) acc[i][j][e] = 0.0f;

    int ntile = K >> 6;
    int ldRow = tid >> 3;           // 0..15
    int ldSeg = tid & 7;
    // 128 threads: A 128 rows (8 its of 16), B 128 rows (8 its of 16)
    #define LOAD_STAGE(t, s)                                                        \
    do {                                                                            \
        int k0_ = (t) << 6;                                                         \
        uint32_t dstA = sb + (s) * STAGE_BYTES + ldRow * 144 + ldSeg * 16;          \
        uint32_t dstB = dstA + TILE_BYTES;                                          \
        _Pragma("unroll")                                                           \
        for (int it = 0; it < 8; it++) {                                            \
            int row = ldRow + it * 16;                                              \
            cpasync16(dstA + it * 16 * 144,                                         \
                      (const uint4*)A + (((size_t)(bm + row) * K + k0_) >> 3) + ldSeg); \
            cpasync16(dstB + it * 16 * 144,                                         \
                      (const uint4*)B + (((size_t)(bn + row) * K + k0_) >> 3) + ldSeg); \
        }                                                                           \
        asm volatile("cp.async.commit_group;");                                     \
    } while (0)

    LOAD_STAGE(0, 0);
    LOAD_STAGE(1, 1);

    for (int t = 0; t < ntile; t++) {
        if (t + 1 < ntile) {
            asm volatile("cp.async.wait_group 1;");
        } else {
            asm volatile("cp.async.wait_group 0;");
        }
        __syncthreads();

        if (t + 2 < ntile) LOAD_STAGE(t + 2, (t + 2) % 3);

        uint32_t offA = sb + (t % 3) * STAGE_BYTES;
        uint32_t offB = offA + TILE_BYTES;

        #pragma unroll
        for (int ks = 0; ks < 4; ks++) {
            uint32_t a[4][4], b[4][4];
            #pragma unroll
            for (int mt = 0; mt < 4; mt++)
                ldm4(a[mt], offA + (uint32_t)(((aRow + mt * 16) * AS_STRIDE) + ks * 16 + aCol) * 2);
            #pragma unroll
            for (int np = 0; np < 4; np++)
                ldm4(b[np], offB + (uint32_t)(((bRow + np * 16) * AS_STRIDE) + ks * 16 + bCol) * 2);
            #pragma unroll
            for (int mt = 0; mt < 4; mt++)
                #pragma unroll
                for (int np = 0; np < 4; np++) {
                    mma16816(acc[mt][np * 2 + 0], a[mt], &b[np][0]);
                    mma16816(acc[mt][np * 2 + 1], a[mt], &b[np][2]);
                }
        }
    }

    #pragma unroll
    for (int mt = 0; mt < 4; mt++) {
        int row0 = bm + warp_m * 64 + mt * 16 + (lane >> 2);
        #pragma unroll
        for (int half = 0; half < 2; half++) {
            int row  = row0 + half * 8;
            int orow = (EPI == 3) ? win2img(row) : row;
            #pragma unroll
            for (int nt = 0; nt < 8; nt++) {
                int col = bn + warp_n * 64 + nt * 8 + (lane & 3) * 2;
                float c0 = acc[mt][nt][half * 2 + 0] + bias[col];
                float c1 = acc[mt][nt][half * 2 + 1] + bias[col + 1];
                if (EPI == 0 || EPI == 1) {
                    if (EPI == 1) { c0 = gelu_tanh(c0); c1 = gelu_tanh(c1); }
                    *(uint32_t*)&Ch[(size_t)row * N + col] =
                        pkh2(__float2half_rn(c0), __float2half_rn(c1));
                } else {
                    size_t o = (size_t)orow * N + col;
                    c0 += res[o]; c1 += res[o + 1];
                    *(float2*)&Cf[o] = make_float2(c0, c1);
                }
            }
        }
    }
}

// ---------------------------------------------------------------------------
// Tensor-core windowed attention (R11/R12 version, unchanged).
// ---------------------------------------------------------------------------
__global__ __launch_bounds__(128)
void attn_kernel(const __half* __restrict__ qkv,
                 const float* __restrict__ table,
                 __half* __restrict__ out) {
    __shared__ __half qs[64][40];
    __shared__ __half ks[64][40];
    __shared__ __half vs[64][40];
    __shared__ float  tbl[225];
    __shared__ int    cnt[64];

    int blk = blockIdx.x;
    int w = blk / NHEADS, h = blk - w * NHEADS;
    int tid = threadIdx.x, lane = tid & 31, wid = tid >> 5;

    const __half* base = qkv + (size_t)w * NTOK * QKV_N + h * HEADD;
    #pragma unroll
    for (int f = tid; f < 256; f += 128) {
        int n = f >> 2, seg = f & 3;
        const __half* rp = base + (size_t)n * QKV_N + seg * 8;
        *(uint4*)&qs[n][seg * 8] = *(const uint4*)rp;
        *(uint4*)&ks[n][seg * 8] = *(const uint4*)(rp + C_DIM);
        *(uint4*)&vs[n][seg * 8] = *(const uint4*)(rp + 2 * C_DIM);
    }
    for (int i = tid; i < 225; i += 128) tbl[i] = table[i * NHEADS + h];
    if (tid < 64) {
        int wi = w & 15;
        int wh = wi >> 2, ww = wi & 3;
        int i = wh * 8 + (tid >> 3);
        int j = ww * 8 + (tid & 7);
        int ri = (i < 24) ? 0 : ((i < 28) ? 1 : 2);
        int rj = (j < 24) ? 0 : ((j < 28) ? 1 : 2);
        cnt[tid] = ri * 3 + rj;
    }
    __syncthreads();

    int lr = lane & 7;
    int aRow = wid * 16 + ((lane >> 3) & 1) * 8 + lr;
    int aCol = (lane >> 4) * 8;
    int bRow8 = ((lane >> 4) & 1) * 8 + lr;
    int bCol = ((lane >> 3) & 1) * 8;

    float s[8][4];
    #pragma unroll
    for (int j = 0; j < 8; j++)
        #pragma unroll
        for (int e = 0; e < 4; e++) s[j][e] = 0.0f;

    #pragma unroll
    for (int kk = 0; kk < 2; kk++) {
        uint32_t a[4];
        ldm4(a, smem_u32(&qs[aRow][kk * 16 + aCol]));
        #pragma unroll
        for (int np = 0; np < 4; np++) {
            uint32_t b[4];
            ldm4(b, smem_u32(&ks[np * 16 + bRow8][kk * 16 + bCol]));
            mma16816(s[np * 2 + 0], a, &b[0]);
            mma16816(s[np * 2 + 1], a, &b[2]);
        }
    }

    int rA = wid * 16 + (lane >> 2);
    int rB = rA + 8;
    int cA = cnt[rA], cB = cnt[rB];
    int r1A = rA >> 3, c1A = rA & 7;
    int r1B = rB >> 3, c1B = rB & 7;

    float mxA = -1e30f, mxB = -1e30f;
    #pragma unroll
    for (int j = 0; j < 8; j++)
        #pragma unroll
        for (int e = 0; e < 2; e++) {
            int m = j * 8 + (lane & 3) * 2 + e;
            int r2 = m >> 3, c2 = m & 7, cm = cnt[m];
            float bA = tbl[(r1A - r2 + 7) * 15 + (c1A - c2 + 7)] + (cA != cm ? -100.0f : 0.0f);
            float bB = tbl[(r1B - r2 + 7) * 15 + (c1B - c2 + 7)] + (cB != cm ? -100.0f : 0.0f);
            s[j][e]     = s[j][e]     * SCALE_ATTN + bA;
            s[j][e + 2] = s[j][e + 2] * SCALE_ATTN + bB;
            mxA = fmaxf(mxA, s[j][e]);
            mxB = fmaxf(mxB, s[j][e + 2]);
        }
    mxA = fmaxf(mxA, __shfl_xor_sync(0xffffffffu, mxA, 1));
    mxA = fmaxf(mxA, __shfl_xor_sync(0xffffffffu, mxA, 2));
    mxB = fmaxf(mxB, __shfl_xor_sync(0xffffffffu, mxB, 1));
    mxB = fmaxf(mxB, __shfl_xor_sync(0xffffffffu, mxB, 2));

    float smA = 0.0f, smB = 0.0f;
    #pragma unroll
    for (int j = 0; j < 8; j++)
        #pragma unroll
        for (int e = 0; e < 2; e++) {
            s[j][e]     = __expf(s[j][e]     - mxA);  smA += s[j][e];
            s[j][e + 2] = __expf(s[j][e + 2] - mxB);  smB += s[j][e + 2];
        }
    smA += __shfl_xor_sync(0xffffffffu, smA, 1);
    smA += __shfl_xor_sync(0xffffffffu, smA, 2);
    smB += __shfl_xor_sync(0xffffffffu, smB, 1);
    smB += __shfl_xor_sync(0xffffffffu, smB, 2);
    float invA = 1.0f / smA, invB = 1.0f / smB;

    float o[4][4];
    #pragma unroll
    for (int j = 0; j < 4; j++)
        #pragma unroll
        for (int e = 0; e < 4; e++) o[j][e] = 0.0f;

    int tvRow = (lane & 7) + ((lane >> 3) & 1) * 8;
    int tvCol = (lane >> 4) * 8;

    #pragma unroll
    for (int kk = 0; kk < 4; kk++) {
        uint32_t a[4];
        a[0] = pkh2(__float2half_rn(s[2 * kk][0] * invA),     __float2half_rn(s[2 * kk][1] * invA));
        a[1] = pkh2(__float2half_rn(s[2 * kk][2] * invB),     __float2half_rn(s[2 * kk][3] * invB));
        a[2] = pkh2(__float2half_rn(s[2 * kk + 1][0] * invA), __float2half_rn(s[2 * kk + 1][1] * invA));
        a[3] = pkh2(__float2half_rn(s[2 * kk + 1][2] * invB), __float2half_rn(s[2 * kk + 1][3] * invB));
        #pragma unroll
        for (int dp = 0; dp < 2; dp++) {
            uint32_t b[4];
            ldm4t(b, smem_u32(&vs[kk * 16 + tvRow][dp * 16 + tvCol]));
            mma16816(o[dp * 2 + 0], a, &b[0]);
            mma16816(o[dp * 2 + 1], a, &b[2]);
        }
    }

    __half* ob = out + (size_t)(w * NTOK) * C_DIM + h * HEADD;
    #pragma unroll
    for (int nt = 0; nt < 4; nt++) {
        int d = nt * 8 + (lane & 3) * 2;
        *(uint32_t*)&ob[(size_t)rA * C_DIM + d] =
            pkh2(__float2half_rn(o[nt][0]), __float2half_rn(o[nt][1]));
        *(uint32_t*)&ob[(size_t)rB * C_DIM + d] =
            pkh2(__float2half_rn(o[nt][2]), __float2half_rn(o[nt][3]));
    }
}

// ---------------------------------------------------------------------------
// launch
// ---------------------------------------------------------------------------
extern "C" void kernel_launch(void* const* d_in, const int* in_sizes, int n_in,
                              void* d_out, int out_size) {
    const float* x      = (const float*)d_in[0];
    const float* n1g    = (const float*)d_in[1];
    const float* n1b    = (const float*)d_in[2];
    const float* qkv_w  = (const float*)d_in[3];
    const float* qkv_b  = (const float*)d_in[4];
    const float* table  = (const float*)d_in[5];
    const float* proj_w = (const float*)d_in[6];
    const float* proj_b = (const float*)d_in[7];
    const float* n2g    = (const float*)d_in[8];
    const float* n2b    = (const float*)d_in[9];
    const float* fc1_w  = (const float*)d_in[10];
    const float* fc1_b  = (const float*)d_in[11];
    const float* fc2_w  = (const float*)d_in[12];
    const float* fc2_b  = (const float*)d_in[13];
    float* out = (float*)d_out;

    static __half *xw, *qkvh, *at, *n2, *hbuf, *wqkv, *wpr, *wf1, *wf2;
    static float *x1;
    static bool init = false;
    if (!init) {
        init = true;
        cudaGetSymbolAddress((void**)&xw,   g_xw);
        cudaGetSymbolAddress((void**)&qkvh, g_qkv);
        cudaGetSymbolAddress((void**)&at,   g_at);
        cudaGetSymbolAddress((void**)&n2,   g_n2);
        cudaGetSymbolAddress((void**)&hbuf, g_h);
        cudaGetSymbolAddress((void**)&wqkv, g_wqkv);
        cudaGetSymbolAddress((void**)&wpr,  g_wpr);
        cudaGetSymbolAddress((void**)&wf1,  g_wf1);
        cudaGetSymbolAddress((void**)&wf2,  g_wf2);
        cudaGetSymbolAddress((void**)&x1,   g_x1);
        cudaFuncSetAttribute(hgemm<0>, cudaFuncAttributeMaxDynamicSharedMemorySize, SMEM_BYTES);
        cudaFuncSetAttribute(hgemm<1>, cudaFuncAttributeMaxDynamicSharedMemorySize, SMEM_BYTES);
        cudaFuncSetAttribute(hgemm<2>, cudaFuncAttributeMaxDynamicSharedMemorySize, SMEM_BYTES);
        cudaFuncSetAttribute(hgemm<3>, cudaFuncAttributeMaxDynamicSharedMemorySize, SMEM_BYTES);
    }

    // 0) fused weight convert + transpose (fp16)
    wconv_all<<<6912, 256>>>(qkv_w, proj_w, fc1_w, fc2_w, wqkv, wpr, wf1, wf2);

    // 1) LN1 + shift + window partition -> fp16
    ln_kernel<true><<<M_TOK, 128>>>(x, n1g, n1b, xw);

    // 2) QKV GEMM -> fp16
    {
        dim3 grid(QKV_N / 128, M_TOK / 128);
        hgemm<0><<<grid, 128, SMEM_BYTES>>>(xw, wqkv, qkv_b, nullptr,
                                            nullptr, qkvh, QKV_N, C_DIM);
    }

    // 3) tensor-core windowed attention -> fp16
    attn_kernel<<<512 * NHEADS, 128>>>(qkvh, table, at);

    // 4) proj + reverse/unshift scatter + residual -> x1 (f32, image layout)
    {
        dim3 grid(C_DIM / 128, M_TOK / 128);
        hgemm<3><<<grid, 128, SMEM_BYTES>>>(at, wpr, proj_b, x,
                                            x1, nullptr, C_DIM, C_DIM);
    }

    // 5) LN2 -> fp16
    ln_kernel<false><<<M_TOK, 128>>>(x1, n2g, n2b, n2);

    // 6) FC1 + GELU -> fp16
    {
        dim3 grid(HIDDEN / 128, M_TOK / 128);
        hgemm<1><<<grid, 128, SMEM_BYTES>>>(n2, wf1, fc1_b, nullptr,
                                            nullptr, hbuf, HIDDEN, C_DIM);
    }

    // 7) FC2 + residual -> out (f32)
    {
        dim3 grid(C_DIM / 128, M_TOK / 128);
        hgemm<2><<<grid, 128, SMEM_BYTES>>>(hbuf, wf2, fc2_b, x1,
                                            out, nullptr, C_DIM, HIDDEN);
    }
}

// round 15
// speedup vs baseline: 1.0312x; 1.0312x over previous
#include <cuda_runtime.h>
#include <cuda_fp16.h>
#include <math.h>
#include <stdint.h>

// ---------------------------------------------------------------------------
// Problem constants
// ---------------------------------------------------------------------------
#define BATCH   32
#define HW      32
#define C_DIM   384
#define NHEADS  12
#define HEADD   32
#define WS      8
#define SS      4
#define NTOK    64
#define M_TOK   (BATCH * HW * HW)      // 32768
#define QKV_N   (3 * C_DIM)            // 1152
#define HIDDEN  (4 * C_DIM)            // 1536
#define SCALE_ATTN 0.17677669529663687f

// ---------------------------------------------------------------------------
// Scratch (device globals; allocation is forbidden)
// ---------------------------------------------------------------------------
__device__ __align__(16) __half g_xw  [(size_t)M_TOK * C_DIM];
__device__ __align__(16) __half g_qkv [(size_t)M_TOK * QKV_N];
__device__ __align__(16) __half g_at  [(size_t)M_TOK * C_DIM];
__device__ __align__(16) float  g_x1  [(size_t)M_TOK * C_DIM];
__device__ __align__(16) __half g_n2  [(size_t)M_TOK * C_DIM];
__device__ __align__(16) __half g_h   [(size_t)M_TOK * HIDDEN];
// transposed fp16 weights [N][K]
__device__ __align__(16) __half g_wqkv[(size_t)QKV_N * C_DIM];
__device__ __align__(16) __half g_wpr [(size_t)C_DIM * C_DIM];
__device__ __align__(16) __half g_wf1 [(size_t)HIDDEN * C_DIM];
__device__ __align__(16) __half g_wf2 [(size_t)C_DIM * HIDDEN];
// precomputed bias+mask tiles: [16 window types][12 heads][64][64] fp16
__device__ __align__(16) __half g_bm  [16 * NHEADS * NTOK * NTOK];

// ---------------------------------------------------------------------------
// helpers
// ---------------------------------------------------------------------------
__device__ __forceinline__ int win2img(int row) {
    int w  = row >> 6;
    int n  = row & 63;
    int b  = w >> 4;
    int wi = w & 15;
    int wh = wi >> 2, ww = wi & 3;
    int r  = n >> 3,  cc = n & 7;
    int i  = (wh * 8 + r + SS) & 31;
    int j  = (ww * 8 + cc + SS) & 31;
    return b * 1024 + i * 32 + j;
}

__device__ __forceinline__ float gelu_tanh(float x) {
    float x3 = x * x * x;
    return 0.5f * x * (1.0f + tanhf(0.7978845608028654f * (x + 0.044715f * x3)));
}

__device__ __forceinline__ uint32_t smem_u32(const void* p) {
    uint32_t a;
    asm("{ .reg .u64 t; cvta.to.shared.u64 t, %1; cvt.u32.u64 %0, t; }" : "=r"(a) : "l"(p));
    return a;
}

__device__ __forceinline__ uint32_t pkh2(__half a, __half b) {
    return (uint32_t)__half_as_ushort(a) | ((uint32_t)__half_as_ushort(b) << 16);
}

__device__ __forceinline__ void cpasync16(uint32_t dst, const void* src) {
    asm volatile("cp.async.cg.shared.global [%0], [%1], 16;" :: "r"(dst), "l"(src));
}

__device__ __forceinline__ void ldm4(uint32_t* r, uint32_t a) {
    asm volatile("ldmatrix.sync.aligned.m8n8.x4.shared.b16 {%0,%1,%2,%3}, [%4];"
                 : "=r"(r[0]), "=r"(r[1]), "=r"(r[2]), "=r"(r[3]) : "r"(a));
}
__device__ __forceinline__ void ldm4t(uint32_t* r, uint32_t a) {
    asm volatile("ldmatrix.sync.aligned.m8n8.x4.trans.shared.b16 {%0,%1,%2,%3}, [%4];"
                 : "=r"(r[0]), "=r"(r[1]), "=r"(r[2]), "=r"(r[3]) : "r"(a));
}
__device__ __forceinline__ void mma16816(float* c, const uint32_t* a, const uint32_t* b) {
    asm volatile("mma.sync.aligned.m16n8k16.row.col.f32.f16.f16.f32 "
                 "{%0,%1,%2,%3}, {%4,%5,%6,%7}, {%8,%9}, {%0,%1,%2,%3};"
                 : "+f"(c[0]), "+f"(c[1]), "+f"(c[2]), "+f"(c[3])
                 : "r"(a[0]), "r"(a[1]), "r"(a[2]), "r"(a[3]), "r"(b[0]), "r"(b[1]));
}

// ---------------------------------------------------------------------------
// single fused weight convert: all four fp32 [K,N] -> fp16 transposed [N,K]
// ---------------------------------------------------------------------------
__global__ void wconv_all(const float* __restrict__ w0, const float* __restrict__ w1,
                          const float* __restrict__ w2, const float* __restrict__ w3,
                          __half* __restrict__ o0, __half* __restrict__ o1,
                          __half* __restrict__ o2, __half* __restrict__ o3) {
    int idx = blockIdx.x * 256 + threadIdx.x;
    const float* w; __half* o; int N, K, off;
    if (idx < 442368)        { w = w0; o = o0; K = 384;  N = 1152; off = idx; }
    else if (idx < 589824)   { w = w1; o = o1; K = 384;  N = 384;  off = idx - 442368; }
    else if (idx < 1179648)  { w = w2; o = o2; K = 384;  N = 1536; off = idx - 589824; }
    else                     { w = w3; o = o3; K = 1536; N = 384;  off = idx - 1179648; }
    int k = off / N, n = off - k * N;
    o[(size_t)n * K + k] = __float2half_rn(w[off]);
}

// ---------------------------------------------------------------------------
// precompute bias+mask tiles: bm[wi][h][n][m] = table[rel(n,m)][h] + mask(wi,n,m)
// 16*12*64*64 = 786432 elements; 3072 blocks x 256 threads
// ---------------------------------------------------------------------------
__global__ void bmconv(const float* __restrict__ table, __half* __restrict__ bm) {
    int idx = blockIdx.x * 256 + threadIdx.x;
    int tile = idx >> 12;            // 0..191 = wi*12 + h
    int e    = idx & 4095;
    int wi = tile / NHEADS, h = tile - wi * NHEADS;
    int n = e >> 6, m = e & 63;
    int wh = wi >> 2, ww = wi & 3;
    int in_ = wh * 8 + (n >> 3), jn = ww * 8 + (n & 7);
    int im_ = wh * 8 + (m >> 3), jm = ww * 8 + (m & 7);
    int cn = ((in_ < 24) ? 0 : (in_ < 28) ? 1 : 2) * 3 + ((jn < 24) ? 0 : (jn < 28) ? 1 : 2);
    int cm = ((im_ < 24) ? 0 : (im_ < 28) ? 1 : 2) * 3 + ((jm < 24) ? 0 : (jm < 28) ? 1 : 2);
    int rel = ((n >> 3) - (m >> 3) + 7) * 15 + ((n & 7) - (m & 7) + 7);
    float v = table[rel * NHEADS + h] + (cn != cm ? -100.0f : 0.0f);
    bm[idx] = __float2half_rn(v);
}

// ---------------------------------------------------------------------------
// LayerNorm -> fp16. SHIFT gathers the shifted-window permutation.
// ---------------------------------------------------------------------------
template <bool SHIFT>
__global__ void ln_kernel(const float* __restrict__ x,
                          const float* __restrict__ gamma,
                          const float* __restrict__ beta,
                          __half* __restrict__ o) {
    int row = blockIdx.x;
    int src = SHIFT ? win2img(row) : row;
    const float* xp = x + (size_t)src * C_DIM;
    int tid = threadIdx.x;

    float v0 = xp[tid], v1 = xp[tid + 128], v2 = xp[tid + 256];
    float s  = v0 + v1 + v2;
    float sq = v0 * v0 + v1 * v1 + v2 * v2;
    #pragma unroll
    for (int off = 16; off > 0; off >>= 1) {
        s  += __shfl_down_sync(0xffffffffu, s,  off);
        sq += __shfl_down_sync(0xffffffffu, sq, off);
    }
    __shared__ float sa[4], sb[4];
    int wp = tid >> 5, ln = tid & 31;
    if (ln == 0) { sa[wp] = s; sb[wp] = sq; }
    __syncthreads();
    s  = sa[0] + sa[1] + sa[2] + sa[3];
    sq = sb[0] + sb[1] + sb[2] + sb[3];

    float mean = s * (1.0f / C_DIM);
    float var  = sq * (1.0f / C_DIM) - mean * mean;
    float inv  = rsqrtf(var + 1e-5f);

    size_t rb = (size_t)row * C_DIM;
    #pragma unroll
    for (int u = 0; u < 3; u++) {
        int c = tid + u * 128;
        float v = (u == 0 ? v0 : u == 1 ? v1 : v2);
        o[rb + c] = __float2half_rn((v - mean) * inv * gamma[c] + beta[c]);
    }
}

// ---------------------------------------------------------------------------
// fp16 HMMA GEMM (exact R9 config = best measured): CTA 128x128, BK=64,
// 256 threads (8 warps 4x2, warp tile 32x64), 2-stage cp.async pipeline.
// EPI 0: bias -> fp16 out                          (qkv)
// EPI 1: bias + gelu -> fp16 out                   (fc1)
// EPI 2: bias + res[m] -> f32 out                  (fc2 + residual, final)
// EPI 3: bias + res[win2img(m)] -> f32 scattered   (proj + reverse + residual)
// ---------------------------------------------------------------------------
#define AS_STRIDE 72                      // halfs per row (64 + 8 pad) = 144 B
#define TILE_BYTES (128 * AS_STRIDE * 2)  // 18432 per tile
#define STAGE_BYTES (2 * TILE_BYTES)      // A + B
#define SMEM_BYTES (2 * STAGE_BYTES)      // 73728

template <int EPI>
__global__ __launch_bounds__(256)
void hgemm(const __half* __restrict__ A, const __half* __restrict__ B,
           const float* __restrict__ bias, const float* __restrict__ res,
           float* __restrict__ Cf, __half* __restrict__ Ch,
           int N, int K) {
    extern __shared__ __align__(16) char sm[];
    uint32_t sb = smem_u32(sm);

    int tid  = threadIdx.x;
    int lane = tid & 31;
    int wid  = tid >> 5;
    int warp_m = wid >> 1;
    int warp_n = wid & 1;
    int bm = blockIdx.y * 128, bn = blockIdx.x * 128;

    int lr = lane & 7;
    int aRow = warp_m * 32 + ((lane >> 3) & 1) * 8 + lr;
    int aCol = (lane >> 4) * 8;
    int bRow = warp_n * 64 + ((lane >> 4) & 1) * 8 + lr;
    int bCol = ((lane >> 3) & 1) * 8;

    float acc[2][8][4];
    #pragma unroll
    for (int i = 0; i < 2; i++)
        #pragma unroll
        for (int j = 0; j < 8; j++)
            #pragma unroll
            for (int e = 0; e < 4; e++) acc[i][j][e] = 0.0f;

    int ntile = K >> 6;
    int ldRow = tid >> 3;
    int ldSeg = tid & 7;
    #define LOAD_STAGE(t, s)                                                        \
    do {                                                                            \
        int k0_ = (t) << 6;                                                         \
        uint32_t dstA = sb + (s) * STAGE_BYTES + ldRow * 144 + ldSeg * 16;          \
        uint32_t dstB = dstA + TILE_BYTES;                                          \
        _Pragma("unroll")                                                           \
        for (int it = 0; it < 4; it++) {                                            \
            int row = ldRow + it * 32;                                              \
            cpasync16(dstA + it * 32 * 144,                                         \
                      (const uint4*)A + (((size_t)(bm + row) * K + k0_) >> 3) + ldSeg); \
            cpasync16(dstB + it * 32 * 144,                                         \
                      (const uint4*)B + (((size_t)(bn + row) * K + k0_) >> 3) + ldSeg); \
        }                                                                           \
        asm volatile("cp.async.commit_group;");                                     \
    } while (0)

    LOAD_STAGE(0, 0);

    for (int t = 0; t < ntile; t++) {
        if (t + 1 < ntile) {
            LOAD_STAGE(t + 1, (t + 1) & 1);
            asm volatile("cp.async.wait_group 1;");
        } else {
            asm volatile("cp.async.wait_group 0;");
        }
        __syncthreads();

        uint32_t offA = sb + (t & 1) * STAGE_BYTES;
        uint32_t offB = offA + TILE_BYTES;

        #pragma unroll
        for (int ks = 0; ks < 4; ks++) {
            uint32_t a[2][4], b[4][4];
            #pragma unroll
            for (int mt = 0; mt < 2; mt++)
                ldm4(a[mt], offA + (uint32_t)(((aRow + mt * 16) * AS_STRIDE) + ks * 16 + aCol) * 2);
            #pragma unroll
            for (int np = 0; np < 4; np++)
                ldm4(b[np], offB + (uint32_t)(((bRow + np * 16) * AS_STRIDE) + ks * 16 + bCol) * 2);
            #pragma unroll
            for (int mt = 0; mt < 2; mt++)
                #pragma unroll
                for (int np = 0; np < 4; np++) {
                    mma16816(acc[mt][np * 2 + 0], a[mt], &b[np][0]);
                    mma16816(acc[mt][np * 2 + 1], a[mt], &b[np][2]);
                }
        }
        __syncthreads();
    }

    #pragma unroll
    for (int mt = 0; mt < 2; mt++) {
        int row0 = bm + warp_m * 32 + mt * 16 + (lane >> 2);
        #pragma unroll
        for (int half = 0; half < 2; half++) {
            int row  = row0 + half * 8;
            int orow = (EPI == 3) ? win2img(row) : row;
            #pragma unroll
            for (int nt = 0; nt < 8; nt++) {
                int col = bn + warp_n * 64 + nt * 8 + (lane & 3) * 2;
                float c0 = acc[mt][nt][half * 2 + 0] + bias[col];
                float c1 = acc[mt][nt][half * 2 + 1] + bias[col + 1];
                if (EPI == 0 || EPI == 1) {
                    if (EPI == 1) { c0 = gelu_tanh(c0); c1 = gelu_tanh(c1); }
                    *(uint32_t*)&Ch[(size_t)row * N + col] =
                        pkh2(__float2half_rn(c0), __float2half_rn(c1));
                } else {
                    size_t o = (size_t)orow * N + col;
                    c0 += res[o]; c1 += res[o + 1];
                    *(float2*)&Cf[o] = make_float2(c0, c1);
                }
            }
        }
    }
}

// ---------------------------------------------------------------------------
// Tensor-core windowed attention with precomputed bias+mask tiles.
// All per-element index math replaced by __half2 loads from g_bm (L2-cached,
// each 8KB tile shared by 32 blocks).
// ---------------------------------------------------------------------------
__global__ __launch_bounds__(128)
void attn_kernel(const __half* __restrict__ qkv,
                 const __half* __restrict__ bmt,
                 __half* __restrict__ out) {
    __shared__ __half qs[64][40];
    __shared__ __half ks[64][40];
    __shared__ __half vs[64][40];

    int blk = blockIdx.x;
    int w = blk / NHEADS, h = blk - w * NHEADS;
    int tid = threadIdx.x, lane = tid & 31, wid = tid >> 5;

    const __half* base = qkv + (size_t)w * NTOK * QKV_N + h * HEADD;
    #pragma unroll
    for (int f = tid; f < 256; f += 128) {
        int n = f >> 2, seg = f & 3;
        const __half* rp = base + (size_t)n * QKV_N + seg * 8;
        *(uint4*)&qs[n][seg * 8] = *(const uint4*)rp;
        *(uint4*)&ks[n][seg * 8] = *(const uint4*)(rp + C_DIM);
        *(uint4*)&vs[n][seg * 8] = *(const uint4*)(rp + 2 * C_DIM);
    }
    __syncthreads();

    int lr = lane & 7;
    int aRow = wid * 16 + ((lane >> 3) & 1) * 8 + lr;
    int aCol = (lane >> 4) * 8;
    int bRow8 = ((lane >> 4) & 1) * 8 + lr;
    int bCol = ((lane >> 3) & 1) * 8;

    float s[8][4];
    #pragma unroll
    for (int j = 0; j < 8; j++)
        #pragma unroll
        for (int e = 0; e < 4; e++) s[j][e] = 0.0f;

    #pragma unroll
    for (int kk = 0; kk < 2; kk++) {
        uint32_t a[4];
        ldm4(a, smem_u32(&qs[aRow][kk * 16 + aCol]));
        #pragma unroll
        for (int np = 0; np < 4; np++) {
            uint32_t b[4];
            ldm4(b, smem_u32(&ks[np * 16 + bRow8][kk * 16 + bCol]));
            mma16816(s[np * 2 + 0], a, &b[0]);
            mma16816(s[np * 2 + 1], a, &b[2]);
        }
    }

    // rows handled by this thread
    int rA = wid * 16 + (lane >> 2);
    int rB = rA + 8;
    int wi = w & 15;
    const __half2* bmA = (const __half2*)(bmt + (((size_t)(wi * NHEADS + h)) << 12) + rA * 64);
    const __half2* bmB = (const __half2*)(bmt + (((size_t)(wi * NHEADS + h)) << 12) + rB * 64);
    int q2 = lane & 3;

    float mxA = -1e30f, mxB = -1e30f;
    #pragma unroll
    for (int j = 0; j < 8; j++) {
        float2 bA = __half22float2(bmA[j * 4 + q2]);
        float2 bB = __half22float2(bmB[j * 4 + q2]);
        s[j][0] = s[j][0] * SCALE_ATTN + bA.x;
        s[j][1] = s[j][1] * SCALE_ATTN + bA.y;
        s[j][2] = s[j][2] * SCALE_ATTN + bB.x;
        s[j][3] = s[j][3] * SCALE_ATTN + bB.y;
        mxA = fmaxf(mxA, fmaxf(s[j][0], s[j][1]));
        mxB = fmaxf(mxB, fmaxf(s[j][2], s[j][3]));
    }
    mxA = fmaxf(mxA, __shfl_xor_sync(0xffffffffu, mxA, 1));
    mxA = fmaxf(mxA, __shfl_xor_sync(0xffffffffu, mxA, 2));
    mxB = fmaxf(mxB, __shfl_xor_sync(0xffffffffu, mxB, 1));
    mxB = fmaxf(mxB, __shfl_xor_sync(0xffffffffu, mxB, 2));

    float smA = 0.0f, smB = 0.0f;
    #pragma unroll
    for (int j = 0; j < 8; j++) {
        s[j][0] = __expf(s[j][0] - mxA);  smA += s[j][0];
        s[j][1] = __expf(s[j][1] - mxA);  smA += s[j][1];
        s[j][2] = __expf(s[j][2] - mxB);  smB += s[j][2];
        s[j][3] = __expf(s[j][3] - mxB);  smB += s[j][3];
    }
    smA += __shfl_xor_sync(0xffffffffu, smA, 1);
    smA += __shfl_xor_sync(0xffffffffu, smA, 2);
    smB += __shfl_xor_sync(0xffffffffu, smB, 1);
    smB += __shfl_xor_sync(0xffffffffu, smB, 2);
    float invA = 1.0f / smA, invB = 1.0f / smB;

    float o[4][4];
    #pragma unroll
    for (int j = 0; j < 4; j++)
        #pragma unroll
        for (int e = 0; e < 4; e++) o[j][e] = 0.0f;

    int tvRow = (lane & 7) + ((lane >> 3) & 1) * 8;
    int tvCol = (lane >> 4) * 8;

    #pragma unroll
    for (int kk = 0; kk < 4; kk++) {
        uint32_t a[4];
        a[0] = pkh2(__float2half_rn(s[2 * kk][0] * invA),     __float2half_rn(s[2 * kk][1] * invA));
        a[1] = pkh2(__float2half_rn(s[2 * kk][2] * invB),     __float2half_rn(s[2 * kk][3] * invB));
        a[2] = pkh2(__float2half_rn(s[2 * kk + 1][0] * invA), __float2half_rn(s[2 * kk + 1][1] * invA));
        a[3] = pkh2(__float2half_rn(s[2 * kk + 1][2] * invB), __float2half_rn(s[2 * kk + 1][3] * invB));
        #pragma unroll
        for (int dp = 0; dp < 2; dp++) {
            uint32_t b[4];
            ldm4t(b, smem_u32(&vs[kk * 16 + tvRow][dp * 16 + tvCol]));
            mma16816(o[dp * 2 + 0], a, &b[0]);
            mma16816(o[dp * 2 + 1], a, &b[2]);
        }
    }

    __half* ob = out + (size_t)(w * NTOK) * C_DIM + h * HEADD;
    #pragma unroll
    for (int nt = 0; nt < 4; nt++) {
        int d = nt * 8 + (lane & 3) * 2;
        *(uint32_t*)&ob[(size_t)rA * C_DIM + d] =
            pkh2(__float2half_rn(o[nt][0]), __float2half_rn(o[nt][1]));
        *(uint32_t*)&ob[(size_t)rB * C_DIM + d] =
            pkh2(__float2half_rn(o[nt][2]), __float2half_rn(o[nt][3]));
    }
}

// ---------------------------------------------------------------------------
// launch
// ---------------------------------------------------------------------------
extern "C" void kernel_launch(void* const* d_in, const int* in_sizes, int n_in,
                              void* d_out, int out_size) {
    const float* x      = (const float*)d_in[0];
    const float* n1g    = (const float*)d_in[1];
    const float* n1b    = (const float*)d_in[2];
    const float* qkv_w  = (const float*)d_in[3];
    const float* qkv_b  = (const float*)d_in[4];
    const float* table  = (const float*)d_in[5];
    const float* proj_w = (const float*)d_in[6];
    const float* proj_b = (const float*)d_in[7];
    const float* n2g    = (const float*)d_in[8];
    const float* n2b    = (const float*)d_in[9];
    const float* fc1_w  = (const float*)d_in[10];
    const float* fc1_b  = (const float*)d_in[11];
    const float* fc2_w  = (const float*)d_in[12];
    const float* fc2_b  = (const float*)d_in[13];
    float* out = (float*)d_out;

    static __half *xw, *qkvh, *at, *n2, *hbuf, *wqkv, *wpr, *wf1, *wf2, *bmp;
    static float *x1;
    static bool init = false;
    if (!init) {
        init = true;
        cudaGetSymbolAddress((void**)&xw,   g_xw);
        cudaGetSymbolAddress((void**)&qkvh, g_qkv);
        cudaGetSymbolAddress((void**)&at,   g_at);
        cudaGetSymbolAddress((void**)&n2,   g_n2);
        cudaGetSymbolAddress((void**)&hbuf, g_h);
        cudaGetSymbolAddress((void**)&wqkv, g_wqkv);
        cudaGetSymbolAddress((void**)&wpr,  g_wpr);
        cudaGetSymbolAddress((void**)&wf1,  g_wf1);
        cudaGetSymbolAddress((void**)&wf2,  g_wf2);
        cudaGetSymbolAddress((void**)&bmp,  g_bm);
        cudaGetSymbolAddress((void**)&x1,   g_x1);
        cudaFuncSetAttribute(hgemm<0>, cudaFuncAttributeMaxDynamicSharedMemorySize, SMEM_BYTES);
        cudaFuncSetAttribute(hgemm<1>, cudaFuncAttributeMaxDynamicSharedMemorySize, SMEM_BYTES);
        cudaFuncSetAttribute(hgemm<2>, cudaFuncAttributeMaxDynamicSharedMemorySize, SMEM_BYTES);
        cudaFuncSetAttribute(hgemm<3>, cudaFuncAttributeMaxDynamicSharedMemorySize, SMEM_BYTES);
    }

    // 0) fused weight convert + bias/mask tile precompute
    wconv_all<<<6912, 256>>>(qkv_w, proj_w, fc1_w, fc2_w, wqkv, wpr, wf1, wf2);
    bmconv<<<3072, 256>>>(table, bmp);

    // 1) LN1 + shift + window partition -> fp16
    ln_kernel<true><<<M_TOK, 128>>>(x, n1g, n1b, xw);

    // 2) QKV GEMM -> fp16
    {
        dim3 grid(QKV_N / 128, M_TOK / 128);
        hgemm<0><<<grid, 256, SMEM_BYTES>>>(xw, wqkv, qkv_b, nullptr,
                                            nullptr, qkvh, QKV_N, C_DIM);
    }

    // 3) tensor-core windowed attention -> fp16
    attn_kernel<<<512 * NHEADS, 128>>>(qkvh, bmp, at);

    // 4) proj + reverse/unshift scatter + residual -> x1 (f32, image layout)
    {
        dim3 grid(C_DIM / 128, M_TOK / 128);
        hgemm<3><<<grid, 256, SMEM_BYTES>>>(at, wpr, proj_b, x,
                                            x1, nullptr, C_DIM, C_DIM);
    }

    // 5) LN2 -> fp16
    ln_kernel<false><<<M_TOK, 128>>>(x1, n2g, n2b, n2);

    // 6) FC1 + GELU -> fp16
    {
        dim3 grid(HIDDEN / 128, M_TOK / 128);
        hgemm<1><<<grid, 256, SMEM_BYTES>>>(n2, wf1, fc1_b, nullptr,
                                            nullptr, hbuf, HIDDEN, C_DIM);
    }

    // 7) FC2 + residual -> out (f32)
    {
        dim3 grid(C_DIM / 128, M_TOK / 128);
        hgemm<2><<<grid, 256, SMEM_BYTES>>>(hbuf, wf2, fc2_b, x1,
                                            out, nullptr, C_DIM, HIDDEN);
    }
}